// round 14
// baseline (speedup 1.0000x reference)
#include <cuda_runtime.h>
#include <math.h>
#include <stdint.h>

#define NNODES 50000
#define NEDGES 800000
#define DCAP 96   // per-node edge-bucket capacity (max degree ~36 at 5 sigma)
#define LOG2E 1.4426950408889634f

// ---------------- scratch (device globals; no allocation allowed) ----------
__device__ __align__(16) float g_h[(size_t)NNODES * 256];   // post-GEMM features (fp32)
__device__ __align__(16) float g_out[(size_t)NNODES * 256]; // aggregated output / next layer input
__device__ __align__(16) float g_s[NNODES * 4];             // per (node,head) src score (x log2e)
__device__ __align__(16) float g_d[NNODES * 4];             // per (node,head) dst score (x log2e)
__device__ int   g_cur[NNODES];                             // per-node degree counter
__device__ int   g_csrc[(size_t)NNODES * DCAP];             // bucketed CSR: source nodes

// ---------------- helpers ----------------
__device__ __forceinline__ uint32_t f2tf32(float x) {
  uint32_t u;
  asm("cvt.rna.tf32.f32 %0, %1;" : "=r"(u) : "f"(x));
  return u;
}
__device__ __forceinline__ void mma_tf32(float* c, const uint32_t* a, const uint32_t* b) {
  asm volatile(
    "mma.sync.aligned.m16n8k8.row.col.f32.tf32.tf32.f32 "
    "{%0,%1,%2,%3}, {%4,%5,%6,%7}, {%8,%9}, {%0,%1,%2,%3};"
    : "+f"(c[0]), "+f"(c[1]), "+f"(c[2]), "+f"(c[3])
    : "r"(a[0]), "r"(a[1]), "r"(a[2]), "r"(a[3]), "r"(b[0]), "r"(b[1]));
}
__device__ __forceinline__ float ex2(float x) {     // == __expf's internal op
  float r;
  asm("ex2.approx.ftz.f32 %0, %1;" : "=f"(r) : "f"(x));
  return r;
}
#define PACK2(dst, x) asm("mov.b64 %0, {%1, %1};" : "=l"(dst) : "f"(x))
#define FMA2(acc, a, b) asm("fma.rn.f32x2 %0, %1, %2, %0;" : "+l"(acc) : "l"(a), "l"(b))
#define UNPK2(lo, hi, p) asm("mov.b64 {%0, %1}, %2;" : "=f"(lo), "=f"(hi) : "l"(p))

// ---------------- tensor-core GEMM: C[M,256] = A[M,K] @ B[K,256] ------------
__global__ __launch_bounds__(256) void gemm_mma(
    const float* __restrict__ A, const float* __restrict__ B, float* __restrict__ C,
    const float* __restrict__ asrc, const float* __restrict__ adst, int M, int K) {
  __shared__ uint32_t As[128][20];   // stride 20: conflict-free frags
  __shared__ uint32_t Bs[16][136];   // stride 136: conflict-free frags
  __shared__ float s_as[256], s_ad[256];
  __shared__ float spart[128][4], dpart[128][4];

  const int tid = threadIdx.x;
  const int wid = tid >> 5, lane = tid & 31;
  const int group = lane >> 2, tid4 = lane & 3;
  const int wm = wid >> 2, wn = wid & 3;
  const int rowBase = blockIdx.y * 128;
  const int colBase = blockIdx.x * 128;

  s_as[tid] = asrc[tid];
  s_ad[tid] = adst[tid];

  float acc[4][4][4];
#pragma unroll
  for (int mi = 0; mi < 4; mi++)
#pragma unroll
    for (int ni = 0; ni < 4; ni++)
#pragma unroll
      for (int q = 0; q < 4; q++) acc[mi][ni][q] = 0.f;

  const int arow = tid >> 2, aq = tid & 3;
  const int brow = tid >> 5, bq = tid & 31;
  const bool aok0 = (rowBase + arow) < M;
  const bool aok1 = (rowBase + arow + 64) < M;

  float4 av0, av1, bv0, bv1;
  const float4 z4 = make_float4(0.f, 0.f, 0.f, 0.f);

  av0 = aok0 ? *reinterpret_cast<const float4*>(&A[(size_t)(rowBase + arow) * K + aq * 4]) : z4;
  av1 = aok1 ? *reinterpret_cast<const float4*>(&A[(size_t)(rowBase + arow + 64) * K + aq * 4]) : z4;
  bv0 = *reinterpret_cast<const float4*>(&B[(size_t)brow * 256 + colBase + bq * 4]);
  bv1 = *reinterpret_cast<const float4*>(&B[(size_t)(brow + 8) * 256 + colBase + bq * 4]);

  for (int k0 = 0; k0 < K; k0 += 16) {
    As[arow][aq * 4 + 0] = f2tf32(av0.x);
    As[arow][aq * 4 + 1] = f2tf32(av0.y);
    As[arow][aq * 4 + 2] = f2tf32(av0.z);
    As[arow][aq * 4 + 3] = f2tf32(av0.w);
    As[arow + 64][aq * 4 + 0] = f2tf32(av1.x);
    As[arow + 64][aq * 4 + 1] = f2tf32(av1.y);
    As[arow + 64][aq * 4 + 2] = f2tf32(av1.z);
    As[arow + 64][aq * 4 + 3] = f2tf32(av1.w);
    Bs[brow][bq * 4 + 0] = f2tf32(bv0.x);
    Bs[brow][bq * 4 + 1] = f2tf32(bv0.y);
    Bs[brow][bq * 4 + 2] = f2tf32(bv0.z);
    Bs[brow][bq * 4 + 3] = f2tf32(bv0.w);
    Bs[brow + 8][bq * 4 + 0] = f2tf32(bv1.x);
    Bs[brow + 8][bq * 4 + 1] = f2tf32(bv1.y);
    Bs[brow + 8][bq * 4 + 2] = f2tf32(bv1.z);
    Bs[brow + 8][bq * 4 + 3] = f2tf32(bv1.w);
    __syncthreads();

    if (k0 + 16 < K) {
      const int kn = k0 + 16;
      av0 = aok0 ? *reinterpret_cast<const float4*>(&A[(size_t)(rowBase + arow) * K + kn + aq * 4]) : z4;
      av1 = aok1 ? *reinterpret_cast<const float4*>(&A[(size_t)(rowBase + arow + 64) * K + kn + aq * 4]) : z4;
      bv0 = *reinterpret_cast<const float4*>(&B[(size_t)(kn + brow) * 256 + colBase + bq * 4]);
      bv1 = *reinterpret_cast<const float4*>(&B[(size_t)(kn + brow + 8) * 256 + colBase + bq * 4]);
    }

#pragma unroll
    for (int ks = 0; ks < 2; ks++) {
      uint32_t af[4][4], bf[4][2];
      const int cc = ks * 8 + tid4;
#pragma unroll
      for (int mi = 0; mi < 4; mi++) {
        const int r = wm * 64 + mi * 16 + group;
        af[mi][0] = As[r][cc];
        af[mi][1] = As[r + 8][cc];
        af[mi][2] = As[r][cc + 4];
        af[mi][3] = As[r + 8][cc + 4];
      }
#pragma unroll
      for (int ni = 0; ni < 4; ni++) {
        const int nn = wn * 32 + ni * 8 + group;
        bf[ni][0] = Bs[ks * 8 + tid4][nn];
        bf[ni][1] = Bs[ks * 8 + tid4 + 4][nn];
      }
#pragma unroll
      for (int mi = 0; mi < 4; mi++)
#pragma unroll
        for (int ni = 0; ni < 4; ni++) mma_tf32(acc[mi][ni], af[mi], bf[ni]);
    }
    __syncthreads();
  }

  // epilogue: fp32 C stores + fused attention dots (scaled by log2e)
#pragma unroll
  for (int mi = 0; mi < 4; mi++) {
    const int lr0 = wm * 64 + mi * 16 + group;
    const int lr1 = lr0 + 8;
    const int r0 = rowBase + lr0;
    const int r1 = rowBase + lr1;
    float s0 = 0.f, d0 = 0.f, s1 = 0.f, d1 = 0.f;
#pragma unroll
    for (int ni = 0; ni < 4; ni++) {
      const int col = colBase + wn * 32 + ni * 8 + tid4 * 2;
      const float c0 = acc[mi][ni][0], c1 = acc[mi][ni][1];
      const float c2 = acc[mi][ni][2], c3 = acc[mi][ni][3];
      const float a0 = s_as[col], a1 = s_as[col + 1];
      const float e0 = s_ad[col], e1 = s_ad[col + 1];
      s0 = fmaf(c0, a0, fmaf(c1, a1, s0));
      d0 = fmaf(c0, e0, fmaf(c1, e1, d0));
      s1 = fmaf(c2, a0, fmaf(c3, a1, s1));
      d1 = fmaf(c2, e0, fmaf(c3, e1, d1));
      if (r0 < M) *reinterpret_cast<float2*>(&C[(size_t)r0 * 256 + col]) = make_float2(c0, c1);
      if (r1 < M) *reinterpret_cast<float2*>(&C[(size_t)r1 * 256 + col]) = make_float2(c2, c3);
    }
#pragma unroll
    for (int o = 1; o < 4; o <<= 1) {
      s0 += __shfl_xor_sync(0xffffffffu, s0, o);
      d0 += __shfl_xor_sync(0xffffffffu, d0, o);
      s1 += __shfl_xor_sync(0xffffffffu, s1, o);
      d1 += __shfl_xor_sync(0xffffffffu, d1, o);
    }
    if (tid4 == 0) {
      spart[lr0][wn] = s0; dpart[lr0][wn] = d0;
      spart[lr1][wn] = s1; dpart[lr1][wn] = d1;
    }
  }
  __syncthreads();
  {
    const int lrow = tid >> 1, hh = tid & 1;
    const int grow = rowBase + lrow;
    if (grow < M) {
      const float s = (spart[lrow][hh * 2] + spart[lrow][hh * 2 + 1]) * LOG2E;
      const float d = (dpart[lrow][hh * 2] + dpart[lrow][hh * 2 + 1]) * LOG2E;
      const int head = blockIdx.x * 2 + hh;
      g_s[grow * 4 + head] = s;
      g_d[grow * 4 + head] = d;
    }
  }
}

// ---------------- GEMM layer 3: N=16, K=256, fused attn (fp32) -------------
__global__ __launch_bounds__(256) void gemm_n16_fused(
    const float* __restrict__ A, const float* __restrict__ B, float* __restrict__ C,
    const float* __restrict__ as3, const float* __restrict__ ad3, int M) {
  const int t = blockIdx.x * blockDim.x + threadIdx.x;
  const int row = t >> 2;
  const int q = t & 3;
  if (row >= M) return;
  const float* a = A + (size_t)row * 256;
  float4 acc = make_float4(0.f, 0.f, 0.f, 0.f);
#pragma unroll 4
  for (int k = 0; k < 256; k += 4) {
    const float4 av = *reinterpret_cast<const float4*>(a + k);
    const float4 b0 = *reinterpret_cast<const float4*>(&B[(k + 0) * 16 + q * 4]);
    const float4 b1 = *reinterpret_cast<const float4*>(&B[(k + 1) * 16 + q * 4]);
    const float4 b2 = *reinterpret_cast<const float4*>(&B[(k + 2) * 16 + q * 4]);
    const float4 b3 = *reinterpret_cast<const float4*>(&B[(k + 3) * 16 + q * 4]);
    acc.x = fmaf(av.x, b0.x, fmaf(av.y, b1.x, fmaf(av.z, b2.x, fmaf(av.w, b3.x, acc.x))));
    acc.y = fmaf(av.x, b0.y, fmaf(av.y, b1.y, fmaf(av.z, b2.y, fmaf(av.w, b3.y, acc.y))));
    acc.z = fmaf(av.x, b0.z, fmaf(av.y, b1.z, fmaf(av.z, b2.z, fmaf(av.w, b3.z, acc.z))));
    acc.w = fmaf(av.x, b0.w, fmaf(av.y, b1.w, fmaf(av.z, b2.w, fmaf(av.w, b3.w, acc.w))));
  }
  *reinterpret_cast<float4*>(&C[(size_t)row * 16 + q * 4]) = acc;
  const float4 a4 = *reinterpret_cast<const float4*>(&as3[q * 4]);
  const float4 d4 = *reinterpret_cast<const float4*>(&ad3[q * 4]);
  float sv = acc.x * a4.x + acc.y * a4.y + acc.z * a4.z + acc.w * a4.w;
  float dv = acc.x * d4.x + acc.y * d4.y + acc.z * d4.z + acc.w * d4.w;
#pragma unroll
  for (int o = 1; o < 4; o <<= 1) {
    sv += __shfl_xor_sync(0xffffffffu, sv, o);
    dv += __shfl_xor_sync(0xffffffffu, dv, o);
  }
  if (q == 0) { g_s[row] = sv * LOG2E; g_d[row] = dv * LOG2E; }
}

// ---------------- bucketed CSR build (no prefix scan) -----------------------
__global__ void k_zero_cur(int n) {
  int i = blockIdx.x * blockDim.x + threadIdx.x;
  if (i < n) g_cur[i] = 0;
}

__global__ void k_scatter(const int* __restrict__ ei, int E, int n) {
  int e = blockIdx.x * blockDim.x + threadIdx.x;
  if (e >= E + n) return;
  int src, dst;
  if (e < E) { src = ei[e]; dst = ei[E + e]; }
  else       { src = dst = e - E; }
  const int pos = atomicAdd(&g_cur[dst], 1);
  if (pos < DCAP) g_csrc[(size_t)dst * DCAP + pos] = src;
}

// ---------------- fully fused aggregation (fp32, f32x2 FMA, 2-edge MLP) -----
// F=256: 32 threads/node (8 fp32 channels = 2x LDG.128), 4 nodes/block of 128.
// Features consumed as packed f32x2 register pairs straight from LDG.128 —
// zero converts, 4 FFMA2 per edge. Scores pre-scaled by log2e -> bare ex2.
__global__ __launch_bounds__(128, 12) void k_agg256(
    const float* __restrict__ h,
    const float* __restrict__ bias, const float* __restrict__ gamma,
    const float* __restrict__ beta, const float* __restrict__ mean,
    const float* __restrict__ var, float* __restrict__ out, int n) {
  const int local = threadIdx.x >> 5;            // node within block (0..3)
  const int lane = threadIdx.x & 31;
  const int node = blockIdx.x * 4 + local;
  if (node >= n) return;
  const int c = lane * 8;                        // 8 fp32 channels
  const int hd = lane >> 3;                      // head (64 channels each)
  const float dscore = g_d[node * 4 + hd];
  int deg = g_cur[node];
  if (deg > DCAP) deg = DCAP;
  const size_t base = (size_t)node * DCAP;
  unsigned long long accp[4] = {0ull, 0ull, 0ull, 0ull};
  float den = 0.f;
  int k = 0;
  for (; k + 1 < deg; k += 2) {
    const int s0 = g_csrc[base + k];
    const int s1 = g_csrc[base + k + 1];
    const float t0 = g_s[s0 * 4 + hd];
    const float t1 = g_s[s1 * 4 + hd];
    const ulonglong2 q00 = *reinterpret_cast<const ulonglong2*>(&h[(size_t)s0 * 256 + c]);
    const ulonglong2 q01 = *reinterpret_cast<const ulonglong2*>(&h[(size_t)s0 * 256 + c + 4]);
    const ulonglong2 q10 = *reinterpret_cast<const ulonglong2*>(&h[(size_t)s1 * 256 + c]);
    const ulonglong2 q11 = *reinterpret_cast<const ulonglong2*>(&h[(size_t)s1 * 256 + c + 4]);
    float v0 = t0 + dscore, v1 = t1 + dscore;
    v0 = fmaxf(v0, 0.2f * v0);                   // leaky relu (scaled domain)
    v1 = fmaxf(v1, 0.2f * v1);
    const float a0 = ex2(v0), a1 = ex2(v1);
    den += a0 + a1;
    unsigned long long p0, p1;
    PACK2(p0, a0);
    PACK2(p1, a1);
    FMA2(accp[0], p0, q00.x); FMA2(accp[1], p0, q00.y);
    FMA2(accp[2], p0, q01.x); FMA2(accp[3], p0, q01.y);
    FMA2(accp[0], p1, q10.x); FMA2(accp[1], p1, q10.y);
    FMA2(accp[2], p1, q11.x); FMA2(accp[3], p1, q11.y);
  }
  if (k < deg) {
    const int s0 = g_csrc[base + k];
    const float t0 = g_s[s0 * 4 + hd];
    const ulonglong2 q00 = *reinterpret_cast<const ulonglong2*>(&h[(size_t)s0 * 256 + c]);
    const ulonglong2 q01 = *reinterpret_cast<const ulonglong2*>(&h[(size_t)s0 * 256 + c + 4]);
    float v0 = t0 + dscore;
    v0 = fmaxf(v0, 0.2f * v0);
    const float a0 = ex2(v0);
    den += a0;
    unsigned long long p0;
    PACK2(p0, a0);
    FMA2(accp[0], p0, q00.x); FMA2(accp[1], p0, q00.y);
    FMA2(accp[2], p0, q01.x); FMA2(accp[3], p0, q01.y);
  }
  float acc[8];
  UNPK2(acc[0], acc[1], accp[0]);
  UNPK2(acc[2], acc[3], accp[1]);
  UNPK2(acc[4], acc[5], accp[2]);
  UNPK2(acc[6], acc[7], accp[3]);
  const float invden = 1.f / den;
  float4 o0, o1;
  {
    const float4 bi = *reinterpret_cast<const float4*>(&bias[c]);
    const float4 ga = *reinterpret_cast<const float4*>(&gamma[c]);
    const float4 be = *reinterpret_cast<const float4*>(&beta[c]);
    const float4 me = *reinterpret_cast<const float4*>(&mean[c]);
    const float4 va = *reinterpret_cast<const float4*>(&var[c]);
    o0.x = fmaxf((acc[0] * invden + bi.x - me.x) * rsqrtf(va.x + 1e-5f) * ga.x + be.x, 0.f);
    o0.y = fmaxf((acc[1] * invden + bi.y - me.y) * rsqrtf(va.y + 1e-5f) * ga.y + be.y, 0.f);
    o0.z = fmaxf((acc[2] * invden + bi.z - me.z) * rsqrtf(va.z + 1e-5f) * ga.z + be.z, 0.f);
    o0.w = fmaxf((acc[3] * invden + bi.w - me.w) * rsqrtf(va.w + 1e-5f) * ga.w + be.w, 0.f);
  }
  {
    const float4 bi = *reinterpret_cast<const float4*>(&bias[c + 4]);
    const float4 ga = *reinterpret_cast<const float4*>(&gamma[c + 4]);
    const float4 be = *reinterpret_cast<const float4*>(&beta[c + 4]);
    const float4 me = *reinterpret_cast<const float4*>(&mean[c + 4]);
    const float4 va = *reinterpret_cast<const float4*>(&var[c + 4]);
    o1.x = fmaxf((acc[4] * invden + bi.x - me.x) * rsqrtf(va.x + 1e-5f) * ga.x + be.x, 0.f);
    o1.y = fmaxf((acc[5] * invden + bi.y - me.y) * rsqrtf(va.y + 1e-5f) * ga.y + be.y, 0.f);
    o1.z = fmaxf((acc[6] * invden + bi.z - me.z) * rsqrtf(va.z + 1e-5f) * ga.z + be.z, 0.f);
    o1.w = fmaxf((acc[7] * invden + bi.w - me.w) * rsqrtf(va.w + 1e-5f) * ga.w + be.w, 0.f);
  }
  *reinterpret_cast<float4*>(&out[(size_t)node * 256 + c]) = o0;
  *reinterpret_cast<float4*>(&out[(size_t)node * 256 + c + 4]) = o1;
}

// F=16 (H=1): fp32, 4-edge unroll, bucketed CSR, ex2 (scores pre-scaled).
__global__ __launch_bounds__(256) void k_agg16(
    const float* __restrict__ h, const float* __restrict__ bias,
    float* __restrict__ out, int n) {
  const int local = threadIdx.x >> 4;
  const int c = threadIdx.x & 15;
  const int node = blockIdx.x * 16 + local;
  if (node >= n) return;
  const float dscore = g_d[node];
  int deg = g_cur[node];
  if (deg > DCAP) deg = DCAP;
  const size_t base = (size_t)node * DCAP;
  float acc = 0.f;
  float den = 0.f;
  int k = 0;
  for (; k + 3 < deg; k += 4) {
    const int s0 = g_csrc[base + k], s1 = g_csrc[base + k + 1];
    const int s2 = g_csrc[base + k + 2], s3 = g_csrc[base + k + 3];
    const float t0 = g_s[s0], t1 = g_s[s1], t2 = g_s[s2], t3 = g_s[s3];
    const float h0 = h[(size_t)s0 * 16 + c];
    const float h1 = h[(size_t)s1 * 16 + c];
    const float h2 = h[(size_t)s2 * 16 + c];
    const float h3 = h[(size_t)s3 * 16 + c];
    float v0 = t0 + dscore, v1 = t1 + dscore, v2 = t2 + dscore, v3 = t3 + dscore;
    v0 = fmaxf(v0, 0.2f * v0);
    v1 = fmaxf(v1, 0.2f * v1);
    v2 = fmaxf(v2, 0.2f * v2);
    v3 = fmaxf(v3, 0.2f * v3);
    const float a0 = ex2(v0), a1 = ex2(v1), a2 = ex2(v2), a3 = ex2(v3);
    den += (a0 + a1) + (a2 + a3);
    acc = fmaf(a0, h0, acc);
    acc = fmaf(a1, h1, acc);
    acc = fmaf(a2, h2, acc);
    acc = fmaf(a3, h3, acc);
  }
  for (; k < deg; k++) {
    const int src = g_csrc[base + k];
    float v = g_s[src] + dscore;
    v = fmaxf(v, 0.2f * v);
    const float al = ex2(v);
    den += al;
    acc = fmaf(al, h[(size_t)src * 16 + c], acc);
  }
  out[(size_t)node * 16 + c] = acc / den + bias[c];
}

// ---------------- host ----------------
extern "C" void kernel_launch(void* const* d_in, const int* in_sizes, int n_in,
                              void* d_out, int out_size) {
  const float* x   = (const float*)d_in[0];
  const int*   ei  = (const int*)d_in[1];       // int32 (JAX x64 disabled)
  const float* W1  = (const float*)d_in[2];
  const float* as1 = (const float*)d_in[3];
  const float* ad1 = (const float*)d_in[4];
  const float* b1  = (const float*)d_in[5];
  const float* g1  = (const float*)d_in[6];
  const float* be1 = (const float*)d_in[7];
  const float* m1  = (const float*)d_in[8];
  const float* v1  = (const float*)d_in[9];
  const float* W2  = (const float*)d_in[10];
  const float* as2 = (const float*)d_in[11];
  const float* ad2 = (const float*)d_in[12];
  const float* b2  = (const float*)d_in[13];
  const float* g2  = (const float*)d_in[14];
  const float* be2 = (const float*)d_in[15];
  const float* m2  = (const float*)d_in[16];
  const float* v2  = (const float*)d_in[17];
  const float* W3  = (const float*)d_in[18];
  const float* as3 = (const float*)d_in[19];
  const float* ad3 = (const float*)d_in[20];
  const float* b3  = (const float*)d_in[21];

  const int n  = in_sizes[0] / 128;    // 50000
  const int E  = in_sizes[1] / 2;      // 800000
  const int ET = E + n;

  float* p_h;   cudaGetSymbolAddress((void**)&p_h,   g_h);
  float* p_out; cudaGetSymbolAddress((void**)&p_out, g_out);

  const int TB = 256;
  const int edgeBlocks = (ET + TB - 1) / TB;
  dim3 mmaGrid(2, (n + 127) / 128);

  // ---- fork a side stream: bucketed CSR build overlaps layer-1 GEMM ----
  cudaStream_t s2;
  cudaEvent_t evFork, evJoin;
  cudaStreamCreateWithFlags(&s2, cudaStreamNonBlocking);
  cudaEventCreateWithFlags(&evFork, cudaEventDisableTiming);
  cudaEventCreateWithFlags(&evJoin, cudaEventDisableTiming);

  cudaEventRecord(evFork, 0);
  cudaStreamWaitEvent(s2, evFork, 0);

  k_zero_cur<<<(n + TB - 1) / TB, TB, 0, s2>>>(n);
  k_scatter<<<edgeBlocks, TB, 0, s2>>>(ei, E, n);
  cudaEventRecord(evJoin, s2);

  // layer-1 GEMM on main stream, concurrent with CSR build
  gemm_mma<<<mmaGrid, 256>>>(x, W1, p_h, as1, ad1, n, 128);

  // join: aggregation needs both GEMM output and CSR
  cudaStreamWaitEvent(0, evJoin, 0);

  // ---- layer 1: aggregate + BN + ReLU ----
  k_agg256<<<(n + 3) / 4, 128>>>(p_h, b1, g1, be1, m1, v1, p_out, n);

  // ---- layer 2: GAT(256 -> 64x4) + BN + ReLU ----
  gemm_mma<<<mmaGrid, 256>>>(p_out, W2, p_h, as2, ad2, n, 256);
  k_agg256<<<(n + 3) / 4, 128>>>(p_h, b2, g2, be2, m2, v2, p_out, n);

  // ---- layer 3: GAT(256 -> 16, single head, no concat) ----
  gemm_n16_fused<<<((size_t)n * 4 + TB - 1) / TB, TB>>>(p_out, W3, p_h, as3, ad3, n);
  k_agg16<<<(n + 15) / 16, 256>>>(p_h, b3, (float*)d_out, n);

  cudaEventDestroy(evFork);
  cudaEventDestroy(evJoin);
  cudaStreamDestroy(s2);
}

// round 15
// speedup vs baseline: 1.2231x; 1.2231x over previous
#include <cuda_runtime.h>
#include <cuda_fp16.h>
#include <math.h>
#include <stdint.h>

#define NNODES 50000
#define NEDGES 800000
#define DCAP 96   // per-node edge-bucket capacity (max degree ~36 at 5 sigma)
#define LOG2E 1.4426950408889634f

// ---------------- scratch (device globals; no allocation allowed) ----------
__device__ __align__(16) __half g_hh[(size_t)NNODES * 256]; // post-GEMM features (fp16, layers 1-2)
__device__ __align__(16) float g_h[(size_t)NNODES * 16];    // post-GEMM features (fp32, layer 3)
__device__ __align__(16) float g_out[(size_t)NNODES * 256]; // aggregated output / next layer input
__device__ __align__(16) float g_s[NNODES * 4];             // per (node,head) src score (x log2e)
__device__ __align__(16) float g_d[NNODES * 4];             // per (node,head) dst score (x log2e)
__device__ int   g_cur[NNODES];                             // per-node degree counter
__device__ __align__(16) int g_csrc[(size_t)NNODES * DCAP]; // bucketed CSR: source nodes

// ---------------- helpers ----------------
__device__ __forceinline__ uint32_t f2tf32(float x) {
  uint32_t u;
  asm("cvt.rna.tf32.f32 %0, %1;" : "=r"(u) : "f"(x));
  return u;
}
__device__ __forceinline__ void mma_tf32(float* c, const uint32_t* a, const uint32_t* b) {
  asm volatile(
    "mma.sync.aligned.m16n8k8.row.col.f32.tf32.tf32.f32 "
    "{%0,%1,%2,%3}, {%4,%5,%6,%7}, {%8,%9}, {%0,%1,%2,%3};"
    : "+f"(c[0]), "+f"(c[1]), "+f"(c[2]), "+f"(c[3])
    : "r"(a[0]), "r"(a[1]), "r"(a[2]), "r"(a[3]), "r"(b[0]), "r"(b[1]));
}
__device__ __forceinline__ float ex2(float x) {   // == __expf's internal op (scores pre-scaled)
  float r;
  asm("ex2.approx.ftz.f32 %0, %1;" : "=f"(r) : "f"(x));
  return r;
}

// ---------------- tensor-core GEMM: C16[M,256] = half(A[M,K] @ B[K,256]) ----
__global__ __launch_bounds__(256) void gemm_mma(
    const float* __restrict__ A, const float* __restrict__ B, __half* __restrict__ C16,
    const float* __restrict__ asrc, const float* __restrict__ adst, int M, int K) {
  __shared__ uint32_t As[128][20];   // stride 20: conflict-free frags
  __shared__ uint32_t Bs[16][136];   // stride 136: conflict-free frags
  __shared__ float s_as[256], s_ad[256];
  __shared__ float spart[128][4], dpart[128][4];

  const int tid = threadIdx.x;
  const int wid = tid >> 5, lane = tid & 31;
  const int group = lane >> 2, tid4 = lane & 3;
  const int wm = wid >> 2, wn = wid & 3;
  const int rowBase = blockIdx.y * 128;
  const int colBase = blockIdx.x * 128;

  s_as[tid] = asrc[tid];
  s_ad[tid] = adst[tid];

  float acc[4][4][4];
#pragma unroll
  for (int mi = 0; mi < 4; mi++)
#pragma unroll
    for (int ni = 0; ni < 4; ni++)
#pragma unroll
      for (int q = 0; q < 4; q++) acc[mi][ni][q] = 0.f;

  const int arow = tid >> 2, aq = tid & 3;
  const int brow = tid >> 5, bq = tid & 31;
  const bool aok0 = (rowBase + arow) < M;
  const bool aok1 = (rowBase + arow + 64) < M;

  float4 av0, av1, bv0, bv1;
  const float4 z4 = make_float4(0.f, 0.f, 0.f, 0.f);

  av0 = aok0 ? *reinterpret_cast<const float4*>(&A[(size_t)(rowBase + arow) * K + aq * 4]) : z4;
  av1 = aok1 ? *reinterpret_cast<const float4*>(&A[(size_t)(rowBase + arow + 64) * K + aq * 4]) : z4;
  bv0 = *reinterpret_cast<const float4*>(&B[(size_t)brow * 256 + colBase + bq * 4]);
  bv1 = *reinterpret_cast<const float4*>(&B[(size_t)(brow + 8) * 256 + colBase + bq * 4]);

  for (int k0 = 0; k0 < K; k0 += 16) {
    As[arow][aq * 4 + 0] = f2tf32(av0.x);
    As[arow][aq * 4 + 1] = f2tf32(av0.y);
    As[arow][aq * 4 + 2] = f2tf32(av0.z);
    As[arow][aq * 4 + 3] = f2tf32(av0.w);
    As[arow + 64][aq * 4 + 0] = f2tf32(av1.x);
    As[arow + 64][aq * 4 + 1] = f2tf32(av1.y);
    As[arow + 64][aq * 4 + 2] = f2tf32(av1.z);
    As[arow + 64][aq * 4 + 3] = f2tf32(av1.w);
    Bs[brow][bq * 4 + 0] = f2tf32(bv0.x);
    Bs[brow][bq * 4 + 1] = f2tf32(bv0.y);
    Bs[brow][bq * 4 + 2] = f2tf32(bv0.z);
    Bs[brow][bq * 4 + 3] = f2tf32(bv0.w);
    Bs[brow + 8][bq * 4 + 0] = f2tf32(bv1.x);
    Bs[brow + 8][bq * 4 + 1] = f2tf32(bv1.y);
    Bs[brow + 8][bq * 4 + 2] = f2tf32(bv1.z);
    Bs[brow + 8][bq * 4 + 3] = f2tf32(bv1.w);
    __syncthreads();

    if (k0 + 16 < K) {
      const int kn = k0 + 16;
      av0 = aok0 ? *reinterpret_cast<const float4*>(&A[(size_t)(rowBase + arow) * K + kn + aq * 4]) : z4;
      av1 = aok1 ? *reinterpret_cast<const float4*>(&A[(size_t)(rowBase + arow + 64) * K + kn + aq * 4]) : z4;
      bv0 = *reinterpret_cast<const float4*>(&B[(size_t)(kn + brow) * 256 + colBase + bq * 4]);
      bv1 = *reinterpret_cast<const float4*>(&B[(size_t)(kn + brow + 8) * 256 + colBase + bq * 4]);
    }

#pragma unroll
    for (int ks = 0; ks < 2; ks++) {
      uint32_t af[4][4], bf[4][2];
      const int cc = ks * 8 + tid4;
#pragma unroll
      for (int mi = 0; mi < 4; mi++) {
        const int r = wm * 64 + mi * 16 + group;
        af[mi][0] = As[r][cc];
        af[mi][1] = As[r + 8][cc];
        af[mi][2] = As[r][cc + 4];
        af[mi][3] = As[r + 8][cc + 4];
      }
#pragma unroll
      for (int ni = 0; ni < 4; ni++) {
        const int nn = wn * 32 + ni * 8 + group;
        bf[ni][0] = Bs[ks * 8 + tid4][nn];
        bf[ni][1] = Bs[ks * 8 + tid4 + 4][nn];
      }
#pragma unroll
      for (int mi = 0; mi < 4; mi++)
#pragma unroll
        for (int ni = 0; ni < 4; ni++) mma_tf32(acc[mi][ni], af[mi], bf[ni]);
    }
    __syncthreads();
  }

  // epilogue: fp16 C stores + fused fp32 attention dots (scaled by log2e)
#pragma unroll
  for (int mi = 0; mi < 4; mi++) {
    const int lr0 = wm * 64 + mi * 16 + group;
    const int lr1 = lr0 + 8;
    const int r0 = rowBase + lr0;
    const int r1 = rowBase + lr1;
    float s0 = 0.f, d0 = 0.f, s1 = 0.f, d1 = 0.f;
#pragma unroll
    for (int ni = 0; ni < 4; ni++) {
      const int col = colBase + wn * 32 + ni * 8 + tid4 * 2;
      const float c0 = acc[mi][ni][0], c1 = acc[mi][ni][1];
      const float c2 = acc[mi][ni][2], c3 = acc[mi][ni][3];
      const float a0 = s_as[col], a1 = s_as[col + 1];
      const float e0 = s_ad[col], e1 = s_ad[col + 1];
      s0 = fmaf(c0, a0, fmaf(c1, a1, s0));
      d0 = fmaf(c0, e0, fmaf(c1, e1, d0));
      s1 = fmaf(c2, a0, fmaf(c3, a1, s1));
      d1 = fmaf(c2, e0, fmaf(c3, e1, d1));
      if (r0 < M) *reinterpret_cast<__half2*>(&C16[(size_t)r0 * 256 + col]) = __floats2half2_rn(c0, c1);
      if (r1 < M) *reinterpret_cast<__half2*>(&C16[(size_t)r1 * 256 + col]) = __floats2half2_rn(c2, c3);
    }
#pragma unroll
    for (int o = 1; o < 4; o <<= 1) {
      s0 += __shfl_xor_sync(0xffffffffu, s0, o);
      d0 += __shfl_xor_sync(0xffffffffu, d0, o);
      s1 += __shfl_xor_sync(0xffffffffu, s1, o);
      d1 += __shfl_xor_sync(0xffffffffu, d1, o);
    }
    if (tid4 == 0) {
      spart[lr0][wn] = s0; dpart[lr0][wn] = d0;
      spart[lr1][wn] = s1; dpart[lr1][wn] = d1;
    }
  }
  __syncthreads();
  {
    const int lrow = tid >> 1, hh = tid & 1;
    const int grow = rowBase + lrow;
    if (grow < M) {
      const float s = (spart[lrow][hh * 2] + spart[lrow][hh * 2 + 1]) * LOG2E;
      const float d = (dpart[lrow][hh * 2] + dpart[lrow][hh * 2 + 1]) * LOG2E;
      const int head = blockIdx.x * 2 + hh;
      g_s[grow * 4 + head] = s;
      g_d[grow * 4 + head] = d;
    }
  }
}

// ---------------- GEMM layer 3: N=16, K=256, fused attn (fp32) -------------
__global__ __launch_bounds__(256) void gemm_n16_fused(
    const float* __restrict__ A, const float* __restrict__ B, float* __restrict__ C,
    const float* __restrict__ as3, const float* __restrict__ ad3, int M) {
  const int t = blockIdx.x * blockDim.x + threadIdx.x;
  const int row = t >> 2;
  const int q = t & 3;
  if (row >= M) return;
  const float* a = A + (size_t)row * 256;
  float4 acc = make_float4(0.f, 0.f, 0.f, 0.f);
#pragma unroll 4
  for (int k = 0; k < 256; k += 4) {
    const float4 av = *reinterpret_cast<const float4*>(a + k);
    const float4 b0 = *reinterpret_cast<const float4*>(&B[(k + 0) * 16 + q * 4]);
    const float4 b1 = *reinterpret_cast<const float4*>(&B[(k + 1) * 16 + q * 4]);
    const float4 b2 = *reinterpret_cast<const float4*>(&B[(k + 2) * 16 + q * 4]);
    const float4 b3 = *reinterpret_cast<const float4*>(&B[(k + 3) * 16 + q * 4]);
    acc.x = fmaf(av.x, b0.x, fmaf(av.y, b1.x, fmaf(av.z, b2.x, fmaf(av.w, b3.x, acc.x))));
    acc.y = fmaf(av.x, b0.y, fmaf(av.y, b1.y, fmaf(av.z, b2.y, fmaf(av.w, b3.y, acc.y))));
    acc.z = fmaf(av.x, b0.z, fmaf(av.y, b1.z, fmaf(av.z, b2.z, fmaf(av.w, b3.z, acc.z))));
    acc.w = fmaf(av.x, b0.w, fmaf(av.y, b1.w, fmaf(av.z, b2.w, fmaf(av.w, b3.w, acc.w))));
  }
  *reinterpret_cast<float4*>(&C[(size_t)row * 16 + q * 4]) = acc;
  const float4 a4 = *reinterpret_cast<const float4*>(&as3[q * 4]);
  const float4 d4 = *reinterpret_cast<const float4*>(&ad3[q * 4]);
  float sv = acc.x * a4.x + acc.y * a4.y + acc.z * a4.z + acc.w * a4.w;
  float dv = acc.x * d4.x + acc.y * d4.y + acc.z * d4.z + acc.w * d4.w;
#pragma unroll
  for (int o = 1; o < 4; o <<= 1) {
    sv += __shfl_xor_sync(0xffffffffu, sv, o);
    dv += __shfl_xor_sync(0xffffffffu, dv, o);
  }
  if (q == 0) { g_s[row] = sv * LOG2E; g_d[row] = dv * LOG2E; }
}

// ---------------- bucketed CSR build (no prefix scan) -----------------------
__global__ void k_zero_cur(int n) {
  int i = blockIdx.x * blockDim.x + threadIdx.x;
  if (i < n) g_cur[i] = 0;
}

__global__ void k_scatter(const int* __restrict__ ei, int E, int n) {
  int e = blockIdx.x * blockDim.x + threadIdx.x;
  if (e >= E + n) return;
  int src, dst;
  if (e < E) { src = ei[e]; dst = ei[E + e]; }
  else       { src = dst = e - E; }
  const int pos = atomicAdd(&g_cur[dst], 1);
  if (pos < DCAP) g_csrc[(size_t)dst * DCAP + pos] = src;
}

// ---------------- fully fused aggregation (fp16 gathers, 4-edge MLP) --------
// F=256: 32 threads/node (8 fp16 channels = 16B loads), 4 nodes/block of 128.
// int4 quad index loads; ex2 on pre-scaled scores; (128,12) launch bounds.
__global__ __launch_bounds__(128, 12) void k_agg256(
    const __half* __restrict__ h,
    const float* __restrict__ bias, const float* __restrict__ gamma,
    const float* __restrict__ beta, const float* __restrict__ mean,
    const float* __restrict__ var, float* __restrict__ out, int n) {
  const int local = threadIdx.x >> 5;            // node within block (0..3)
  const int lane = threadIdx.x & 31;
  const int node = blockIdx.x * 4 + local;
  if (node >= n) return;
  const int c = lane * 8;                        // 8 fp16 channels
  const int hd = lane >> 3;                      // head (64 channels each)
  const float dscore = g_d[node * 4 + hd];
  int deg = g_cur[node];
  if (deg > DCAP) deg = DCAP;
  const size_t base = (size_t)node * DCAP;
  float acc[8];
#pragma unroll
  for (int i = 0; i < 8; i++) acc[i] = 0.f;
  float den = 0.f;
  int k = 0;
  for (; k + 3 < deg; k += 4) {
    const int4 sq = *reinterpret_cast<const int4*>(&g_csrc[base + k]);
    const int s0 = sq.x, s1 = sq.y, s2 = sq.z, s3 = sq.w;
    const float t0 = g_s[s0 * 4 + hd];
    const float t1 = g_s[s1 * 4 + hd];
    const float t2 = g_s[s2 * 4 + hd];
    const float t3 = g_s[s3 * 4 + hd];
    const uint4 r0 = *reinterpret_cast<const uint4*>(&h[(size_t)s0 * 256 + c]);
    const uint4 r1 = *reinterpret_cast<const uint4*>(&h[(size_t)s1 * 256 + c]);
    const uint4 r2 = *reinterpret_cast<const uint4*>(&h[(size_t)s2 * 256 + c]);
    const uint4 r3 = *reinterpret_cast<const uint4*>(&h[(size_t)s3 * 256 + c]);
    float v0 = t0 + dscore, v1 = t1 + dscore, v2 = t2 + dscore, v3 = t3 + dscore;
    v0 = fmaxf(v0, 0.2f * v0);                   // leaky relu (scaled domain)
    v1 = fmaxf(v1, 0.2f * v1);
    v2 = fmaxf(v2, 0.2f * v2);
    v3 = fmaxf(v3, 0.2f * v3);
    const float a0 = ex2(v0), a1 = ex2(v1), a2 = ex2(v2), a3 = ex2(v3);
    den += (a0 + a1) + (a2 + a3);
    {
      const float2 f0 = __half22float2(*reinterpret_cast<const __half2*>(&r0.x));
      const float2 f1 = __half22float2(*reinterpret_cast<const __half2*>(&r0.y));
      const float2 f2 = __half22float2(*reinterpret_cast<const __half2*>(&r0.z));
      const float2 f3 = __half22float2(*reinterpret_cast<const __half2*>(&r0.w));
      acc[0] = fmaf(a0, f0.x, acc[0]); acc[1] = fmaf(a0, f0.y, acc[1]);
      acc[2] = fmaf(a0, f1.x, acc[2]); acc[3] = fmaf(a0, f1.y, acc[3]);
      acc[4] = fmaf(a0, f2.x, acc[4]); acc[5] = fmaf(a0, f2.y, acc[5]);
      acc[6] = fmaf(a0, f3.x, acc[6]); acc[7] = fmaf(a0, f3.y, acc[7]);
    }
    {
      const float2 f0 = __half22float2(*reinterpret_cast<const __half2*>(&r1.x));
      const float2 f1 = __half22float2(*reinterpret_cast<const __half2*>(&r1.y));
      const float2 f2 = __half22float2(*reinterpret_cast<const __half2*>(&r1.z));
      const float2 f3 = __half22float2(*reinterpret_cast<const __half2*>(&r1.w));
      acc[0] = fmaf(a1, f0.x, acc[0]); acc[1] = fmaf(a1, f0.y, acc[1]);
      acc[2] = fmaf(a1, f1.x, acc[2]); acc[3] = fmaf(a1, f1.y, acc[3]);
      acc[4] = fmaf(a1, f2.x, acc[4]); acc[5] = fmaf(a1, f2.y, acc[5]);
      acc[6] = fmaf(a1, f3.x, acc[6]); acc[7] = fmaf(a1, f3.y, acc[7]);
    }
    {
      const float2 f0 = __half22float2(*reinterpret_cast<const __half2*>(&r2.x));
      const float2 f1 = __half22float2(*reinterpret_cast<const __half2*>(&r2.y));
      const float2 f2 = __half22float2(*reinterpret_cast<const __half2*>(&r2.z));
      const float2 f3 = __half22float2(*reinterpret_cast<const __half2*>(&r2.w));
      acc[0] = fmaf(a2, f0.x, acc[0]); acc[1] = fmaf(a2, f0.y, acc[1]);
      acc[2] = fmaf(a2, f1.x, acc[2]); acc[3] = fmaf(a2, f1.y, acc[3]);
      acc[4] = fmaf(a2, f2.x, acc[4]); acc[5] = fmaf(a2, f2.y, acc[5]);
      acc[6] = fmaf(a2, f3.x, acc[6]); acc[7] = fmaf(a2, f3.y, acc[7]);
    }
    {
      const float2 f0 = __half22float2(*reinterpret_cast<const __half2*>(&r3.x));
      const float2 f1 = __half22float2(*reinterpret_cast<const __half2*>(&r3.y));
      const float2 f2 = __half22float2(*reinterpret_cast<const __half2*>(&r3.z));
      const float2 f3 = __half22float2(*reinterpret_cast<const __half2*>(&r3.w));
      acc[0] = fmaf(a3, f0.x, acc[0]); acc[1] = fmaf(a3, f0.y, acc[1]);
      acc[2] = fmaf(a3, f1.x, acc[2]); acc[3] = fmaf(a3, f1.y, acc[3]);
      acc[4] = fmaf(a3, f2.x, acc[4]); acc[5] = fmaf(a3, f2.y, acc[5]);
      acc[6] = fmaf(a3, f3.x, acc[6]); acc[7] = fmaf(a3, f3.y, acc[7]);
    }
  }
  for (; k < deg; k++) {
    const int src = g_csrc[base + k];
    float v = g_s[src * 4 + hd] + dscore;
    const uint4 raw = *reinterpret_cast<const uint4*>(&h[(size_t)src * 256 + c]);
    v = fmaxf(v, 0.2f * v);
    const float al = ex2(v);
    den += al;
    const float2 f0 = __half22float2(*reinterpret_cast<const __half2*>(&raw.x));
    const float2 f1 = __half22float2(*reinterpret_cast<const __half2*>(&raw.y));
    const float2 f2 = __half22float2(*reinterpret_cast<const __half2*>(&raw.z));
    const float2 f3 = __half22float2(*reinterpret_cast<const __half2*>(&raw.w));
    acc[0] = fmaf(al, f0.x, acc[0]); acc[1] = fmaf(al, f0.y, acc[1]);
    acc[2] = fmaf(al, f1.x, acc[2]); acc[3] = fmaf(al, f1.y, acc[3]);
    acc[4] = fmaf(al, f2.x, acc[4]); acc[5] = fmaf(al, f2.y, acc[5]);
    acc[6] = fmaf(al, f3.x, acc[6]); acc[7] = fmaf(al, f3.y, acc[7]);
  }
  const float invden = 1.f / den;
  float4 o0, o1;
  {
    const float4 bi = *reinterpret_cast<const float4*>(&bias[c]);
    const float4 ga = *reinterpret_cast<const float4*>(&gamma[c]);
    const float4 be = *reinterpret_cast<const float4*>(&beta[c]);
    const float4 me = *reinterpret_cast<const float4*>(&mean[c]);
    const float4 va = *reinterpret_cast<const float4*>(&var[c]);
    o0.x = fmaxf((acc[0] * invden + bi.x - me.x) * rsqrtf(va.x + 1e-5f) * ga.x + be.x, 0.f);
    o0.y = fmaxf((acc[1] * invden + bi.y - me.y) * rsqrtf(va.y + 1e-5f) * ga.y + be.y, 0.f);
    o0.z = fmaxf((acc[2] * invden + bi.z - me.z) * rsqrtf(va.z + 1e-5f) * ga.z + be.z, 0.f);
    o0.w = fmaxf((acc[3] * invden + bi.w - me.w) * rsqrtf(va.w + 1e-5f) * ga.w + be.w, 0.f);
  }
  {
    const float4 bi = *reinterpret_cast<const float4*>(&bias[c + 4]);
    const float4 ga = *reinterpret_cast<const float4*>(&gamma[c + 4]);
    const float4 be = *reinterpret_cast<const float4*>(&beta[c + 4]);
    const float4 me = *reinterpret_cast<const float4*>(&mean[c + 4]);
    const float4 va = *reinterpret_cast<const float4*>(&var[c + 4]);
    o1.x = fmaxf((acc[4] * invden + bi.x - me.x) * rsqrtf(va.x + 1e-5f) * ga.x + be.x, 0.f);
    o1.y = fmaxf((acc[5] * invden + bi.y - me.y) * rsqrtf(va.y + 1e-5f) * ga.y + be.y, 0.f);
    o1.z = fmaxf((acc[6] * invden + bi.z - me.z) * rsqrtf(va.z + 1e-5f) * ga.z + be.z, 0.f);
    o1.w = fmaxf((acc[7] * invden + bi.w - me.w) * rsqrtf(va.w + 1e-5f) * ga.w + be.w, 0.f);
  }
  *reinterpret_cast<float4*>(&out[(size_t)node * 256 + c]) = o0;
  *reinterpret_cast<float4*>(&out[(size_t)node * 256 + c + 4]) = o1;
}

// F=16 (H=1): fp32, int4 idx loads, ex2 (pre-scaled), bucketed CSR.
__global__ __launch_bounds__(256) void k_agg16(
    const float* __restrict__ h, const float* __restrict__ bias,
    float* __restrict__ out, int n) {
  const int local = threadIdx.x >> 4;
  const int c = threadIdx.x & 15;
  const int node = blockIdx.x * 16 + local;
  if (node >= n) return;
  const float dscore = g_d[node];
  int deg = g_cur[node];
  if (deg > DCAP) deg = DCAP;
  const size_t base = (size_t)node * DCAP;
  float acc = 0.f;
  float den = 0.f;
  int k = 0;
  for (; k + 3 < deg; k += 4) {
    const int4 sq = *reinterpret_cast<const int4*>(&g_csrc[base + k]);
    const int s0 = sq.x, s1 = sq.y, s2 = sq.z, s3 = sq.w;
    const float t0 = g_s[s0], t1 = g_s[s1], t2 = g_s[s2], t3 = g_s[s3];
    const float h0 = h[(size_t)s0 * 16 + c];
    const float h1 = h[(size_t)s1 * 16 + c];
    const float h2 = h[(size_t)s2 * 16 + c];
    const float h3 = h[(size_t)s3 * 16 + c];
    float v0 = t0 + dscore, v1 = t1 + dscore, v2 = t2 + dscore, v3 = t3 + dscore;
    v0 = fmaxf(v0, 0.2f * v0);
    v1 = fmaxf(v1, 0.2f * v1);
    v2 = fmaxf(v2, 0.2f * v2);
    v3 = fmaxf(v3, 0.2f * v3);
    const float a0 = ex2(v0), a1 = ex2(v1), a2 = ex2(v2), a3 = ex2(v3);
    den += (a0 + a1) + (a2 + a3);
    acc = fmaf(a0, h0, acc);
    acc = fmaf(a1, h1, acc);
    acc = fmaf(a2, h2, acc);
    acc = fmaf(a3, h3, acc);
  }
  for (; k < deg; k++) {
    const int src = g_csrc[base + k];
    float v = g_s[src] + dscore;
    v = fmaxf(v, 0.2f * v);
    const float al = ex2(v);
    den += al;
    acc = fmaf(al, h[(size_t)src * 16 + c], acc);
  }
  out[(size_t)node * 16 + c] = acc / den + bias[c];
}

// ---------------- host ----------------
extern "C" void kernel_launch(void* const* d_in, const int* in_sizes, int n_in,
                              void* d_out, int out_size) {
  const float* x   = (const float*)d_in[0];
  const int*   ei  = (const int*)d_in[1];       // int32 (JAX x64 disabled)
  const float* W1  = (const float*)d_in[2];
  const float* as1 = (const float*)d_in[3];
  const float* ad1 = (const float*)d_in[4];
  const float* b1  = (const float*)d_in[5];
  const float* g1  = (const float*)d_in[6];
  const float* be1 = (const float*)d_in[7];
  const float* m1  = (const float*)d_in[8];
  const float* v1  = (const float*)d_in[9];
  const float* W2  = (const float*)d_in[10];
  const float* as2 = (const float*)d_in[11];
  const float* ad2 = (const float*)d_in[12];
  const float* b2  = (const float*)d_in[13];
  const float* g2  = (const float*)d_in[14];
  const float* be2 = (const float*)d_in[15];
  const float* m2  = (const float*)d_in[16];
  const float* v2  = (const float*)d_in[17];
  const float* W3  = (const float*)d_in[18];
  const float* as3 = (const float*)d_in[19];
  const float* ad3 = (const float*)d_in[20];
  const float* b3  = (const float*)d_in[21];

  const int n  = in_sizes[0] / 128;    // 50000
  const int E  = in_sizes[1] / 2;      // 800000
  const int ET = E + n;

  __half* p_hh; cudaGetSymbolAddress((void**)&p_hh, g_hh);
  float* p_h;   cudaGetSymbolAddress((void**)&p_h,   g_h);
  float* p_out; cudaGetSymbolAddress((void**)&p_out, g_out);

  const int TB = 256;
  const int edgeBlocks = (ET + TB - 1) / TB;
  dim3 mmaGrid(2, (n + 127) / 128);

  // ---- fork a side stream: bucketed CSR build overlaps layer-1 GEMM ----
  cudaStream_t s2;
  cudaEvent_t evFork, evJoin;
  cudaStreamCreateWithFlags(&s2, cudaStreamNonBlocking);
  cudaEventCreateWithFlags(&evFork, cudaEventDisableTiming);
  cudaEventCreateWithFlags(&evJoin, cudaEventDisableTiming);

  cudaEventRecord(evFork, 0);
  cudaStreamWaitEvent(s2, evFork, 0);

  k_zero_cur<<<(n + TB - 1) / TB, TB, 0, s2>>>(n);
  k_scatter<<<edgeBlocks, TB, 0, s2>>>(ei, E, n);
  cudaEventRecord(evJoin, s2);

  // layer-1 GEMM on main stream, concurrent with CSR build
  gemm_mma<<<mmaGrid, 256>>>(x, W1, p_hh, as1, ad1, n, 128);

  // join: aggregation needs both GEMM output and CSR
  cudaStreamWaitEvent(0, evJoin, 0);

  // ---- layer 1: aggregate + BN + ReLU ----
  k_agg256<<<(n + 3) / 4, 128>>>(p_hh, b1, g1, be1, m1, v1, p_out, n);

  // ---- layer 2: GAT(256 -> 64x4) + BN + ReLU ----
  gemm_mma<<<mmaGrid, 256>>>(p_out, W2, p_hh, as2, ad2, n, 256);
  k_agg256<<<(n + 3) / 4, 128>>>(p_hh, b2, g2, be2, m2, v2, p_out, n);

  // ---- layer 3: GAT(256 -> 16, single head, no concat) ----
  gemm_n16_fused<<<((size_t)n * 4 + TB - 1) / TB, TB>>>(p_out, W3, p_h, as3, ad3, n);
  k_agg16<<<(n + 15) / 16, 256>>>(p_h, b3, (float*)d_out, n);

  cudaEventDestroy(evFork);
  cudaEventDestroy(evJoin);
  cudaStreamDestroy(s2);
}

// round 16
// speedup vs baseline: 1.2350x; 1.0097x over previous
#include <cuda_runtime.h>
#include <cuda_fp16.h>
#include <math.h>
#include <stdint.h>

#define NNODES 50000
#define NEDGES 800000
#define DCAP 96   // per-node edge-bucket capacity (max degree ~36 at 5 sigma)
#define LOG2E 1.4426950408889634f

// ---------------- scratch (device globals; no allocation allowed) ----------
__device__ __align__(16) __half g_hh[(size_t)NNODES * 256]; // post-GEMM features (fp16, layers 1-2)
__device__ __align__(16) float g_h[(size_t)NNODES * 16];    // post-GEMM features (fp32, layer 3)
__device__ __align__(16) float g_out[(size_t)NNODES * 256]; // aggregated output / next layer input
__device__ __align__(16) float g_s[NNODES * 4];             // per (node,head) src score (x log2e)
__device__ __align__(16) float g_d[NNODES * 4];             // per (node,head) dst score (x log2e)
__device__ int   g_cur[NNODES];                             // per-node degree counter
__device__ __align__(16) int g_csrc[(size_t)NNODES * DCAP]; // bucketed CSR: source nodes

// ---------------- helpers ----------------
__device__ __forceinline__ uint32_t f2tf32(float x) {
  uint32_t u;
  asm("cvt.rna.tf32.f32 %0, %1;" : "=r"(u) : "f"(x));
  return u;
}
__device__ __forceinline__ void mma_tf32(float* c, const uint32_t* a, const uint32_t* b) {
  asm volatile(
    "mma.sync.aligned.m16n8k8.row.col.f32.tf32.tf32.f32 "
    "{%0,%1,%2,%3}, {%4,%5,%6,%7}, {%8,%9}, {%0,%1,%2,%3};"
    : "+f"(c[0]), "+f"(c[1]), "+f"(c[2]), "+f"(c[3])
    : "r"(a[0]), "r"(a[1]), "r"(a[2]), "r"(a[3]), "r"(b[0]), "r"(b[1]));
}
__device__ __forceinline__ float ex2(float x) {   // == __expf's internal op (scores pre-scaled)
  float r;
  asm("ex2.approx.ftz.f32 %0, %1;" : "=f"(r) : "f"(x));
  return r;
}

// ---------------- tensor-core GEMM: C16[M,256] = half(A[M,K] @ B[K,256]) ----
__global__ __launch_bounds__(256) void gemm_mma(
    const float* __restrict__ A, const float* __restrict__ B, __half* __restrict__ C16,
    const float* __restrict__ asrc, const float* __restrict__ adst, int M, int K) {
  __shared__ uint32_t As[128][20];   // stride 20: conflict-free frags
  __shared__ uint32_t Bs[16][136];   // stride 136: conflict-free frags
  __shared__ float s_as[256], s_ad[256];
  __shared__ float spart[128][4], dpart[128][4];

  const int tid = threadIdx.x;
  const int wid = tid >> 5, lane = tid & 31;
  const int group = lane >> 2, tid4 = lane & 3;
  const int wm = wid >> 2, wn = wid & 3;
  const int rowBase = blockIdx.y * 128;
  const int colBase = blockIdx.x * 128;

  s_as[tid] = asrc[tid];
  s_ad[tid] = adst[tid];

  float acc[4][4][4];
#pragma unroll
  for (int mi = 0; mi < 4; mi++)
#pragma unroll
    for (int ni = 0; ni < 4; ni++)
#pragma unroll
      for (int q = 0; q < 4; q++) acc[mi][ni][q] = 0.f;

  const int arow = tid >> 2, aq = tid & 3;
  const int brow = tid >> 5, bq = tid & 31;
  const bool aok0 = (rowBase + arow) < M;
  const bool aok1 = (rowBase + arow + 64) < M;

  float4 av0, av1, bv0, bv1;
  const float4 z4 = make_float4(0.f, 0.f, 0.f, 0.f);

  av0 = aok0 ? *reinterpret_cast<const float4*>(&A[(size_t)(rowBase + arow) * K + aq * 4]) : z4;
  av1 = aok1 ? *reinterpret_cast<const float4*>(&A[(size_t)(rowBase + arow + 64) * K + aq * 4]) : z4;
  bv0 = *reinterpret_cast<const float4*>(&B[(size_t)brow * 256 + colBase + bq * 4]);
  bv1 = *reinterpret_cast<const float4*>(&B[(size_t)(brow + 8) * 256 + colBase + bq * 4]);

  for (int k0 = 0; k0 < K; k0 += 16) {
    As[arow][aq * 4 + 0] = f2tf32(av0.x);
    As[arow][aq * 4 + 1] = f2tf32(av0.y);
    As[arow][aq * 4 + 2] = f2tf32(av0.z);
    As[arow][aq * 4 + 3] = f2tf32(av0.w);
    As[arow + 64][aq * 4 + 0] = f2tf32(av1.x);
    As[arow + 64][aq * 4 + 1] = f2tf32(av1.y);
    As[arow + 64][aq * 4 + 2] = f2tf32(av1.z);
    As[arow + 64][aq * 4 + 3] = f2tf32(av1.w);
    Bs[brow][bq * 4 + 0] = f2tf32(bv0.x);
    Bs[brow][bq * 4 + 1] = f2tf32(bv0.y);
    Bs[brow][bq * 4 + 2] = f2tf32(bv0.z);
    Bs[brow][bq * 4 + 3] = f2tf32(bv0.w);
    Bs[brow + 8][bq * 4 + 0] = f2tf32(bv1.x);
    Bs[brow + 8][bq * 4 + 1] = f2tf32(bv1.y);
    Bs[brow + 8][bq * 4 + 2] = f2tf32(bv1.z);
    Bs[brow + 8][bq * 4 + 3] = f2tf32(bv1.w);
    __syncthreads();

    if (k0 + 16 < K) {
      const int kn = k0 + 16;
      av0 = aok0 ? *reinterpret_cast<const float4*>(&A[(size_t)(rowBase + arow) * K + kn + aq * 4]) : z4;
      av1 = aok1 ? *reinterpret_cast<const float4*>(&A[(size_t)(rowBase + arow + 64) * K + kn + aq * 4]) : z4;
      bv0 = *reinterpret_cast<const float4*>(&B[(size_t)(kn + brow) * 256 + colBase + bq * 4]);
      bv1 = *reinterpret_cast<const float4*>(&B[(size_t)(kn + brow + 8) * 256 + colBase + bq * 4]);
    }

#pragma unroll
    for (int ks = 0; ks < 2; ks++) {
      uint32_t af[4][4], bf[4][2];
      const int cc = ks * 8 + tid4;
#pragma unroll
      for (int mi = 0; mi < 4; mi++) {
        const int r = wm * 64 + mi * 16 + group;
        af[mi][0] = As[r][cc];
        af[mi][1] = As[r + 8][cc];
        af[mi][2] = As[r][cc + 4];
        af[mi][3] = As[r + 8][cc + 4];
      }
#pragma unroll
      for (int ni = 0; ni < 4; ni++) {
        const int nn = wn * 32 + ni * 8 + group;
        bf[ni][0] = Bs[ks * 8 + tid4][nn];
        bf[ni][1] = Bs[ks * 8 + tid4 + 4][nn];
      }
#pragma unroll
      for (int mi = 0; mi < 4; mi++)
#pragma unroll
        for (int ni = 0; ni < 4; ni++) mma_tf32(acc[mi][ni], af[mi], bf[ni]);
    }
    __syncthreads();
  }

  // epilogue: fp16 C stores + fused fp32 attention dots (scaled by log2e)
#pragma unroll
  for (int mi = 0; mi < 4; mi++) {
    const int lr0 = wm * 64 + mi * 16 + group;
    const int lr1 = lr0 + 8;
    const int r0 = rowBase + lr0;
    const int r1 = rowBase + lr1;
    float s0 = 0.f, d0 = 0.f, s1 = 0.f, d1 = 0.f;
#pragma unroll
    for (int ni = 0; ni < 4; ni++) {
      const int col = colBase + wn * 32 + ni * 8 + tid4 * 2;
      const float c0 = acc[mi][ni][0], c1 = acc[mi][ni][1];
      const float c2 = acc[mi][ni][2], c3 = acc[mi][ni][3];
      const float a0 = s_as[col], a1 = s_as[col + 1];
      const float e0 = s_ad[col], e1 = s_ad[col + 1];
      s0 = fmaf(c0, a0, fmaf(c1, a1, s0));
      d0 = fmaf(c0, e0, fmaf(c1, e1, d0));
      s1 = fmaf(c2, a0, fmaf(c3, a1, s1));
      d1 = fmaf(c2, e0, fmaf(c3, e1, d1));
      if (r0 < M) *reinterpret_cast<__half2*>(&C16[(size_t)r0 * 256 + col]) = __floats2half2_rn(c0, c1);
      if (r1 < M) *reinterpret_cast<__half2*>(&C16[(size_t)r1 * 256 + col]) = __floats2half2_rn(c2, c3);
    }
#pragma unroll
    for (int o = 1; o < 4; o <<= 1) {
      s0 += __shfl_xor_sync(0xffffffffu, s0, o);
      d0 += __shfl_xor_sync(0xffffffffu, d0, o);
      s1 += __shfl_xor_sync(0xffffffffu, s1, o);
      d1 += __shfl_xor_sync(0xffffffffu, d1, o);
    }
    if (tid4 == 0) {
      spart[lr0][wn] = s0; dpart[lr0][wn] = d0;
      spart[lr1][wn] = s1; dpart[lr1][wn] = d1;
    }
  }
  __syncthreads();
  {
    const int lrow = tid >> 1, hh = tid & 1;
    const int grow = rowBase + lrow;
    if (grow < M) {
      const float s = (spart[lrow][hh * 2] + spart[lrow][hh * 2 + 1]) * LOG2E;
      const float d = (dpart[lrow][hh * 2] + dpart[lrow][hh * 2 + 1]) * LOG2E;
      const int head = blockIdx.x * 2 + hh;
      g_s[grow * 4 + head] = s;
      g_d[grow * 4 + head] = d;
    }
  }
}

// ---------------- GEMM layer 3: N=16, K=256, fused attn (fp32) -------------
__global__ __launch_bounds__(256) void gemm_n16_fused(
    const float* __restrict__ A, const float* __restrict__ B, float* __restrict__ C,
    const float* __restrict__ as3, const float* __restrict__ ad3, int M) {
  const int t = blockIdx.x * blockDim.x + threadIdx.x;
  const int row = t >> 2;
  const int q = t & 3;
  if (row >= M) return;
  const float* a = A + (size_t)row * 256;
  float4 acc = make_float4(0.f, 0.f, 0.f, 0.f);
#pragma unroll 4
  for (int k = 0; k < 256; k += 4) {
    const float4 av = *reinterpret_cast<const float4*>(a + k);
    const float4 b0 = *reinterpret_cast<const float4*>(&B[(k + 0) * 16 + q * 4]);
    const float4 b1 = *reinterpret_cast<const float4*>(&B[(k + 1) * 16 + q * 4]);
    const float4 b2 = *reinterpret_cast<const float4*>(&B[(k + 2) * 16 + q * 4]);
    const float4 b3 = *reinterpret_cast<const float4*>(&B[(k + 3) * 16 + q * 4]);
    acc.x = fmaf(av.x, b0.x, fmaf(av.y, b1.x, fmaf(av.z, b2.x, fmaf(av.w, b3.x, acc.x))));
    acc.y = fmaf(av.x, b0.y, fmaf(av.y, b1.y, fmaf(av.z, b2.y, fmaf(av.w, b3.y, acc.y))));
    acc.z = fmaf(av.x, b0.z, fmaf(av.y, b1.z, fmaf(av.z, b2.z, fmaf(av.w, b3.z, acc.z))));
    acc.w = fmaf(av.x, b0.w, fmaf(av.y, b1.w, fmaf(av.z, b2.w, fmaf(av.w, b3.w, acc.w))));
  }
  *reinterpret_cast<float4*>(&C[(size_t)row * 16 + q * 4]) = acc;
  const float4 a4 = *reinterpret_cast<const float4*>(&as3[q * 4]);
  const float4 d4 = *reinterpret_cast<const float4*>(&ad3[q * 4]);
  float sv = acc.x * a4.x + acc.y * a4.y + acc.z * a4.z + acc.w * a4.w;
  float dv = acc.x * d4.x + acc.y * d4.y + acc.z * d4.z + acc.w * d4.w;
#pragma unroll
  for (int o = 1; o < 4; o <<= 1) {
    sv += __shfl_xor_sync(0xffffffffu, sv, o);
    dv += __shfl_xor_sync(0xffffffffu, dv, o);
  }
  if (q == 0) { g_s[row] = sv * LOG2E; g_d[row] = dv * LOG2E; }
}

// ---------------- bucketed CSR build (no prefix scan) -----------------------
__global__ void k_zero_cur(int n) {
  int i = blockIdx.x * blockDim.x + threadIdx.x;
  if (i < n) g_cur[i] = 0;
}

__global__ void k_scatter(const int* __restrict__ ei, int E, int n) {
  int e = blockIdx.x * blockDim.x + threadIdx.x;
  if (e >= E + n) return;
  int src, dst;
  if (e < E) { src = ei[e]; dst = ei[E + e]; }
  else       { src = dst = e - E; }
  const int pos = atomicAdd(&g_cur[dst], 1);
  if (pos < DCAP) g_csrc[(size_t)dst * DCAP + pos] = src;
}

// ---------------- fully fused aggregation (fp16 gathers, 4-edge MLP) --------
// F=256: 32 threads/node, 2 nodes/block of 64. (64,24): 1536 thr/SM, and
// max-of-2 (not 4) degree tail per block to cut intra-block imbalance.
__global__ __launch_bounds__(64, 24) void k_agg256(
    const __half* __restrict__ h,
    const float* __restrict__ bias, const float* __restrict__ gamma,
    const float* __restrict__ beta, const float* __restrict__ mean,
    const float* __restrict__ var, float* __restrict__ out, int n) {
  const int local = threadIdx.x >> 5;            // node within block (0..1)
  const int lane = threadIdx.x & 31;
  const int node = blockIdx.x * 2 + local;
  if (node >= n) return;
  const int c = lane * 8;                        // 8 fp16 channels
  const int hd = lane >> 3;                      // head (64 channels each)
  const float dscore = g_d[node * 4 + hd];
  int deg = g_cur[node];
  if (deg > DCAP) deg = DCAP;
  const size_t base = (size_t)node * DCAP;
  float acc[8];
#pragma unroll
  for (int i = 0; i < 8; i++) acc[i] = 0.f;
  float den = 0.f;
  int k = 0;
  for (; k + 3 < deg; k += 4) {
    const int4 sq = *reinterpret_cast<const int4*>(&g_csrc[base + k]);
    const int s0 = sq.x, s1 = sq.y, s2 = sq.z, s3 = sq.w;
    const float t0 = g_s[s0 * 4 + hd];
    const float t1 = g_s[s1 * 4 + hd];
    const float t2 = g_s[s2 * 4 + hd];
    const float t3 = g_s[s3 * 4 + hd];
    const uint4 r0 = *reinterpret_cast<const uint4*>(&h[(size_t)s0 * 256 + c]);
    const uint4 r1 = *reinterpret_cast<const uint4*>(&h[(size_t)s1 * 256 + c]);
    const uint4 r2 = *reinterpret_cast<const uint4*>(&h[(size_t)s2 * 256 + c]);
    const uint4 r3 = *reinterpret_cast<const uint4*>(&h[(size_t)s3 * 256 + c]);
    float v0 = t0 + dscore, v1 = t1 + dscore, v2 = t2 + dscore, v3 = t3 + dscore;
    v0 = fmaxf(v0, 0.2f * v0);                   // leaky relu (scaled domain)
    v1 = fmaxf(v1, 0.2f * v1);
    v2 = fmaxf(v2, 0.2f * v2);
    v3 = fmaxf(v3, 0.2f * v3);
    const float a0 = ex2(v0), a1 = ex2(v1), a2 = ex2(v2), a3 = ex2(v3);
    den += (a0 + a1) + (a2 + a3);
    {
      const float2 f0 = __half22float2(*reinterpret_cast<const __half2*>(&r0.x));
      const float2 f1 = __half22float2(*reinterpret_cast<const __half2*>(&r0.y));
      const float2 f2 = __half22float2(*reinterpret_cast<const __half2*>(&r0.z));
      const float2 f3 = __half22float2(*reinterpret_cast<const __half2*>(&r0.w));
      acc[0] = fmaf(a0, f0.x, acc[0]); acc[1] = fmaf(a0, f0.y, acc[1]);
      acc[2] = fmaf(a0, f1.x, acc[2]); acc[3] = fmaf(a0, f1.y, acc[3]);
      acc[4] = fmaf(a0, f2.x, acc[4]); acc[5] = fmaf(a0, f2.y, acc[5]);
      acc[6] = fmaf(a0, f3.x, acc[6]); acc[7] = fmaf(a0, f3.y, acc[7]);
    }
    {
      const float2 f0 = __half22float2(*reinterpret_cast<const __half2*>(&r1.x));
      const float2 f1 = __half22float2(*reinterpret_cast<const __half2*>(&r1.y));
      const float2 f2 = __half22float2(*reinterpret_cast<const __half2*>(&r1.z));
      const float2 f3 = __half22float2(*reinterpret_cast<const __half2*>(&r1.w));
      acc[0] = fmaf(a1, f0.x, acc[0]); acc[1] = fmaf(a1, f0.y, acc[1]);
      acc[2] = fmaf(a1, f1.x, acc[2]); acc[3] = fmaf(a1, f1.y, acc[3]);
      acc[4] = fmaf(a1, f2.x, acc[4]); acc[5] = fmaf(a1, f2.y, acc[5]);
      acc[6] = fmaf(a1, f3.x, acc[6]); acc[7] = fmaf(a1, f3.y, acc[7]);
    }
    {
      const float2 f0 = __half22float2(*reinterpret_cast<const __half2*>(&r2.x));
      const float2 f1 = __half22float2(*reinterpret_cast<const __half2*>(&r2.y));
      const float2 f2 = __half22float2(*reinterpret_cast<const __half2*>(&r2.z));
      const float2 f3 = __half22float2(*reinterpret_cast<const __half2*>(&r2.w));
      acc[0] = fmaf(a2, f0.x, acc[0]); acc[1] = fmaf(a2, f0.y, acc[1]);
      acc[2] = fmaf(a2, f1.x, acc[2]); acc[3] = fmaf(a2, f1.y, acc[3]);
      acc[4] = fmaf(a2, f2.x, acc[4]); acc[5] = fmaf(a2, f2.y, acc[5]);
      acc[6] = fmaf(a2, f3.x, acc[6]); acc[7] = fmaf(a2, f3.y, acc[7]);
    }
    {
      const float2 f0 = __half22float2(*reinterpret_cast<const __half2*>(&r3.x));
      const float2 f1 = __half22float2(*reinterpret_cast<const __half2*>(&r3.y));
      const float2 f2 = __half22float2(*reinterpret_cast<const __half2*>(&r3.z));
      const float2 f3 = __half22float2(*reinterpret_cast<const __half2*>(&r3.w));
      acc[0] = fmaf(a3, f0.x, acc[0]); acc[1] = fmaf(a3, f0.y, acc[1]);
      acc[2] = fmaf(a3, f1.x, acc[2]); acc[3] = fmaf(a3, f1.y, acc[3]);
      acc[4] = fmaf(a3, f2.x, acc[4]); acc[5] = fmaf(a3, f2.y, acc[5]);
      acc[6] = fmaf(a3, f3.x, acc[6]); acc[7] = fmaf(a3, f3.y, acc[7]);
    }
  }
  for (; k < deg; k++) {
    const int src = g_csrc[base + k];
    float v = g_s[src * 4 + hd] + dscore;
    const uint4 raw = *reinterpret_cast<const uint4*>(&h[(size_t)src * 256 + c]);
    v = fmaxf(v, 0.2f * v);
    const float al = ex2(v);
    den += al;
    const float2 f0 = __half22float2(*reinterpret_cast<const __half2*>(&raw.x));
    const float2 f1 = __half22float2(*reinterpret_cast<const __half2*>(&raw.y));
    const float2 f2 = __half22float2(*reinterpret_cast<const __half2*>(&raw.z));
    const float2 f3 = __half22float2(*reinterpret_cast<const __half2*>(&raw.w));
    acc[0] = fmaf(al, f0.x, acc[0]); acc[1] = fmaf(al, f0.y, acc[1]);
    acc[2] = fmaf(al, f1.x, acc[2]); acc[3] = fmaf(al, f1.y, acc[3]);
    acc[4] = fmaf(al, f2.x, acc[4]); acc[5] = fmaf(al, f2.y, acc[5]);
    acc[6] = fmaf(al, f3.x, acc[6]); acc[7] = fmaf(al, f3.y, acc[7]);
  }
  const float invden = 1.f / den;
  float4 o0, o1;
  {
    const float4 bi = *reinterpret_cast<const float4*>(&bias[c]);
    const float4 ga = *reinterpret_cast<const float4*>(&gamma[c]);
    const float4 be = *reinterpret_cast<const float4*>(&beta[c]);
    const float4 me = *reinterpret_cast<const float4*>(&mean[c]);
    const float4 va = *reinterpret_cast<const float4*>(&var[c]);
    o0.x = fmaxf((acc[0] * invden + bi.x - me.x) * rsqrtf(va.x + 1e-5f) * ga.x + be.x, 0.f);
    o0.y = fmaxf((acc[1] * invden + bi.y - me.y) * rsqrtf(va.y + 1e-5f) * ga.y + be.y, 0.f);
    o0.z = fmaxf((acc[2] * invden + bi.z - me.z) * rsqrtf(va.z + 1e-5f) * ga.z + be.z, 0.f);
    o0.w = fmaxf((acc[3] * invden + bi.w - me.w) * rsqrtf(va.w + 1e-5f) * ga.w + be.w, 0.f);
  }
  {
    const float4 bi = *reinterpret_cast<const float4*>(&bias[c + 4]);
    const float4 ga = *reinterpret_cast<const float4*>(&gamma[c + 4]);
    const float4 be = *reinterpret_cast<const float4*>(&beta[c + 4]);
    const float4 me = *reinterpret_cast<const float4*>(&mean[c + 4]);
    const float4 va = *reinterpret_cast<const float4*>(&var[c + 4]);
    o1.x = fmaxf((acc[4] * invden + bi.x - me.x) * rsqrtf(va.x + 1e-5f) * ga.x + be.x, 0.f);
    o1.y = fmaxf((acc[5] * invden + bi.y - me.y) * rsqrtf(va.y + 1e-5f) * ga.y + be.y, 0.f);
    o1.z = fmaxf((acc[6] * invden + bi.z - me.z) * rsqrtf(va.z + 1e-5f) * ga.z + be.z, 0.f);
    o1.w = fmaxf((acc[7] * invden + bi.w - me.w) * rsqrtf(va.w + 1e-5f) * ga.w + be.w, 0.f);
  }
  *reinterpret_cast<float4*>(&out[(size_t)node * 256 + c]) = o0;
  *reinterpret_cast<float4*>(&out[(size_t)node * 256 + c + 4]) = o1;
}

// F=16 (H=1): fp32, int4 idx loads, ex2 (pre-scaled), bucketed CSR.
__global__ __launch_bounds__(256) void k_agg16(
    const float* __restrict__ h, const float* __restrict__ bias,
    float* __restrict__ out, int n) {
  const int local = threadIdx.x >> 4;
  const int c = threadIdx.x & 15;
  const int node = blockIdx.x * 16 + local;
  if (node >= n) return;
  const float dscore = g_d[node];
  int deg = g_cur[node];
  if (deg > DCAP) deg = DCAP;
  const size_t base = (size_t)node * DCAP;
  float acc = 0.f;
  float den = 0.f;
  int k = 0;
  for (; k + 3 < deg; k += 4) {
    const int4 sq = *reinterpret_cast<const int4*>(&g_csrc[base + k]);
    const int s0 = sq.x, s1 = sq.y, s2 = sq.z, s3 = sq.w;
    const float t0 = g_s[s0], t1 = g_s[s1], t2 = g_s[s2], t3 = g_s[s3];
    const float h0 = h[(size_t)s0 * 16 + c];
    const float h1 = h[(size_t)s1 * 16 + c];
    const float h2 = h[(size_t)s2 * 16 + c];
    const float h3 = h[(size_t)s3 * 16 + c];
    float v0 = t0 + dscore, v1 = t1 + dscore, v2 = t2 + dscore, v3 = t3 + dscore;
    v0 = fmaxf(v0, 0.2f * v0);
    v1 = fmaxf(v1, 0.2f * v1);
    v2 = fmaxf(v2, 0.2f * v2);
    v3 = fmaxf(v3, 0.2f * v3);
    const float a0 = ex2(v0), a1 = ex2(v1), a2 = ex2(v2), a3 = ex2(v3);
    den += (a0 + a1) + (a2 + a3);
    acc = fmaf(a0, h0, acc);
    acc = fmaf(a1, h1, acc);
    acc = fmaf(a2, h2, acc);
    acc = fmaf(a3, h3, acc);
  }
  for (; k < deg; k++) {
    const int src = g_csrc[base + k];
    float v = g_s[src] + dscore;
    v = fmaxf(v, 0.2f * v);
    const float al = ex2(v);
    den += al;
    acc = fmaf(al, h[(size_t)src * 16 + c], acc);
  }
  out[(size_t)node * 16 + c] = acc / den + bias[c];
}

// ---------------- host ----------------
extern "C" void kernel_launch(void* const* d_in, const int* in_sizes, int n_in,
                              void* d_out, int out_size) {
  const float* x   = (const float*)d_in[0];
  const int*   ei  = (const int*)d_in[1];       // int32 (JAX x64 disabled)
  const float* W1  = (const float*)d_in[2];
  const float* as1 = (const float*)d_in[3];
  const float* ad1 = (const float*)d_in[4];
  const float* b1  = (const float*)d_in[5];
  const float* g1  = (const float*)d_in[6];
  const float* be1 = (const float*)d_in[7];
  const float* m1  = (const float*)d_in[8];
  const float* v1  = (const float*)d_in[9];
  const float* W2  = (const float*)d_in[10];
  const float* as2 = (const float*)d_in[11];
  const float* ad2 = (const float*)d_in[12];
  const float* b2  = (const float*)d_in[13];
  const float* g2  = (const float*)d_in[14];
  const float* be2 = (const float*)d_in[15];
  const float* m2  = (const float*)d_in[16];
  const float* v2  = (const float*)d_in[17];
  const float* W3  = (const float*)d_in[18];
  const float* as3 = (const float*)d_in[19];
  const float* ad3 = (const float*)d_in[20];
  const float* b3  = (const float*)d_in[21];

  const int n  = in_sizes[0] / 128;    // 50000
  const int E  = in_sizes[1] / 2;      // 800000
  const int ET = E + n;

  __half* p_hh; cudaGetSymbolAddress((void**)&p_hh, g_hh);
  float* p_h;   cudaGetSymbolAddress((void**)&p_h,   g_h);
  float* p_out; cudaGetSymbolAddress((void**)&p_out, g_out);

  const int TB = 256;
  const int edgeBlocks = (ET + TB - 1) / TB;
  dim3 mmaGrid(2, (n + 127) / 128);

  // ---- fork a side stream: bucketed CSR build overlaps layer-1 GEMM ----
  cudaStream_t s2;
  cudaEvent_t evFork, evJoin;
  cudaStreamCreateWithFlags(&s2, cudaStreamNonBlocking);
  cudaEventCreateWithFlags(&evFork, cudaEventDisableTiming);
  cudaEventCreateWithFlags(&evJoin, cudaEventDisableTiming);

  cudaEventRecord(evFork, 0);
  cudaStreamWaitEvent(s2, evFork, 0);

  k_zero_cur<<<(n + TB - 1) / TB, TB, 0, s2>>>(n);
  k_scatter<<<edgeBlocks, TB, 0, s2>>>(ei, E, n);
  cudaEventRecord(evJoin, s2);

  // layer-1 GEMM on main stream, concurrent with CSR build
  gemm_mma<<<mmaGrid, 256>>>(x, W1, p_hh, as1, ad1, n, 128);

  // join: aggregation needs both GEMM output and CSR
  cudaStreamWaitEvent(0, evJoin, 0);

  // ---- layer 1: aggregate + BN + ReLU ----
  k_agg256<<<(n + 1) / 2, 64>>>(p_hh, b1, g1, be1, m1, v1, p_out, n);

  // ---- layer 2: GAT(256 -> 64x4) + BN + ReLU ----
  gemm_mma<<<mmaGrid, 256>>>(p_out, W2, p_hh, as2, ad2, n, 256);
  k_agg256<<<(n + 1) / 2, 64>>>(p_hh, b2, g2, be2, m2, v2, p_out, n);

  // ---- layer 3: GAT(256 -> 16, single head, no concat) ----
  gemm_n16_fused<<<((size_t)n * 4 + TB - 1) / TB, TB>>>(p_out, W3, p_h, as3, ad3, n);
  k_agg16<<<(n + 15) / 16, 256>>>(p_h, b3, (float*)d_out, n);

  cudaEventDestroy(evFork);
  cudaEventDestroy(evJoin);
  cudaStreamDestroy(s2);
}